// round 9
// baseline (speedup 1.0000x reference)
#include <cuda_runtime.h>
#include <cstdint>

#define DB 64
#define DS 2048
#define DI 64
#define DH 128

typedef unsigned long long u64;

// ---------------- scratch (__device__ globals) -------------------------------
__device__ float g_wx0 [DB * DS * DH];   // x @ w0 (precomputed by gemm)
__device__ float g_out0[DB * DS * DH];   // layer-0 outputs
__device__ float g_wx1a[DB * DS * 64];   // out0 @ w1[:,0:64] (producer helpers)
__device__ int   g_prog[DB * 32];        // [b*32]=p0  [+8]=pwx1a

// ---------------- packed f32x2 helpers ---------------------------------------
__device__ __forceinline__ u64 ffma2(u64 a, u64 b, u64 c) {
    u64 d; asm("fma.rn.f32x2 %0, %1, %2, %3;" : "=l"(d) : "l"(a), "l"(b), "l"(c)); return d;
}
__device__ __forceinline__ u64 fadd2(u64 a, u64 b) {
    u64 d; asm("add.rn.f32x2 %0, %1, %2;" : "=l"(d) : "l"(a), "l"(b)); return d;
}
__device__ __forceinline__ u64 dup2(float x) {
    u64 d; asm("mov.b64 %0, {%1, %2};" : "=l"(d) : "f"(x), "f"(x)); return d;
}
__device__ __forceinline__ u64 pk2(float lo, float hi) {
    u64 d; asm("mov.b64 %0, {%1, %2};" : "=l"(d) : "f"(lo), "f"(hi)); return d;
}
__device__ __forceinline__ float2 unp2(u64 v) {
    float lo, hi; asm("mov.b64 {%0, %1}, %2;" : "=f"(lo), "=f"(hi) : "l"(v));
    return make_float2(lo, hi);
}

// ---------------- fast gates (validated, rel_err ~1.3e-7) ---------------------
__device__ __forceinline__ float sigm_fast(float x) {
    float t, r;
    asm("ex2.approx.f32 %0, %1;" : "=f"(t) : "f"(-1.4426950408889634f * x));
    asm("rcp.approx.f32 %0, %1;" : "=f"(r) : "f"(1.0f + t));
    return r;
}
__device__ __forceinline__ float tanh_fast(float x) {
    float t, r;
    asm("ex2.approx.f32 %0, %1;" : "=f"(t) : "f"(-2.8853900817779268f * x));
    asm("rcp.approx.f32 %0, %1;" : "=f"(r) : "f"(1.0f + t));
    return __fmaf_rn(2.0f, r, -1.0f);
}

// ---------------- flags --------------------------------------------------------
__device__ __forceinline__ int ld_acq(const int* p) {
    int v; asm volatile("ld.acquire.gpu.b32 %0, [%1];" : "=r"(v) : "l"(p)); return v;
}
__device__ __forceinline__ void st_rel(int* p, int v) {
    asm volatile("st.release.gpu.b32 [%0], %1;" :: "l"(p), "r"(v));
}
__device__ __forceinline__ void spin_ge(const int* p, int target) {
    while (ld_acq(p) < target) __nanosleep(32);
}

__global__ void reset_kernel() {
    int i = blockIdx.x * blockDim.x + threadIdx.x;
    if (i < DB * 32) g_prog[i] = 0;
}

// ============================================================================
// GEMM: OUT[row, 0:128] = X[row, 0:K] @ W[K,128]. One row per thread. (~70us)
// ============================================================================
template<int K>
__global__ void __launch_bounds__(256, 1) gemm_rows(
    const float* __restrict__ X, const float* __restrict__ W, float* __restrict__ OUT)
{
    extern __shared__ float ws[];
    for (int i = threadIdx.x; i < K * DH / 4; i += 256)
        reinterpret_cast<float4*>(ws)[i] = reinterpret_cast<const float4*>(W)[i];
    __syncthreads();

    int row = blockIdx.x * 256 + threadIdx.x;
    const float* xr = X + (size_t)row * K;
    float xv[K];
    #pragma unroll
    for (int i = 0; i < K / 4; i++) {
        float4 v = reinterpret_cast<const float4*>(xr)[i];
        xv[4*i] = v.x; xv[4*i+1] = v.y; xv[4*i+2] = v.z; xv[4*i+3] = v.w;
    }
    const u64* wsu = reinterpret_cast<const u64*>(ws);
    float* outr = OUT + (size_t)row * DH;

    #pragma unroll 1
    for (int cb = 0; cb < 16; cb++) {
        u64 a0 = 0, a1 = 0, a2 = 0, a3 = 0;
        #pragma unroll 16
        for (int k = 0; k < K; k++) {
            u64 xd = dup2(xv[k]);
            const u64* wr = wsu + k * (DH / 2) + cb * 4;
            a0 = ffma2(xd, wr[0], a0);
            a1 = ffma2(xd, wr[1], a1);
            a2 = ffma2(xd, wr[2], a2);
            a3 = ffma2(xd, wr[3], a3);
        }
        float2 r0 = unp2(a0), r1 = unp2(a1), r2 = unp2(a2), r3 = unp2(a3);
        reinterpret_cast<float4*>(outr)[cb*2]     = make_float4(r0.x, r0.y, r1.x, r1.y);
        reinterpret_cast<float4*>(outr)[cb*2 + 1] = make_float4(r2.x, r2.y, r3.x, r3.y);
    }
}

// ---------------- matvec fragments --------------------------------------------
// full 128-k dot for one column: 32 ULL2 broadcast loads, 64 FFMA2, 4 accs.
__device__ __forceinline__ float mv128(const float* row, const u64* uk) {
    const ulonglong2* hp = reinterpret_cast<const ulonglong2*>(row);
    u64 a0 = 0, a1 = 0, a2 = 0, a3 = 0;
    #pragma unroll
    for (int i = 0; i < 32; i += 2) {
        ulonglong2 q0 = hp[i], q1 = hp[i + 1];
        a0 = ffma2(q0.x, uk[2*i + 0], a0);
        a1 = ffma2(q0.y, uk[2*i + 1], a1);
        a2 = ffma2(q1.x, uk[2*i + 2], a2);
        a3 = ffma2(q1.y, uk[2*i + 3], a3);
    }
    u64 s = fadd2(fadd2(a0, a1), fadd2(a2, a3));
    float2 p = unp2(s);
    return p.x + p.y;
}
// half-k (64) dot for one column (helper, kh-split): 16 ULL2, 32 FFMA2.
__device__ __forceinline__ u64 mv64(const float* src, const u64* uw) {
    const ulonglong2* hp = reinterpret_cast<const ulonglong2*>(src);
    u64 a0 = 0, a1 = 0, a2 = 0, a3 = 0;
    #pragma unroll
    for (int i = 0; i < 16; i += 2) {
        ulonglong2 q0 = hp[i], q1 = hp[i + 1];
        a0 = ffma2(q0.x, uw[2*i + 0], a0);
        a1 = ffma2(q0.y, uw[2*i + 1], a1);
        a2 = ffma2(q1.x, uw[2*i + 2], a2);
        a3 = ffma2(q1.y, uw[2*i + 3], a3);
    }
    return fadd2(fadd2(a0, a1), fadd2(a2, a3));
}
__device__ __forceinline__ float comb2(u64 acc) {
    acc = fadd2(acc, __shfl_xor_sync(0xFFFFFFFFu, acc, 1));
    float2 p = unp2(acc);
    return p.x + p.y;
}

// ============================================================================
// Pipe kernel: grid = 128 (64 producer + 64 consumer), 256 threads, 1 CTA/SM.
// ============================================================================
__global__ void __launch_bounds__(256, 1) pipe_kernel(
    const float* __restrict__ u0, const float* __restrict__ u1,
    const float* __restrict__ w1,
    const float* __restrict__ bg0, const float* __restrict__ bu0,
    const float* __restrict__ zeta0, const float* __restrict__ nu0,
    const float* __restrict__ lambd0, const float* __restrict__ gamma0,
    const float* __restrict__ bg1, const float* __restrict__ bu1,
    const float* __restrict__ zeta1, const float* __restrict__ nu1,
    const float* __restrict__ lambd1, const float* __restrict__ gamma1,
    float* __restrict__ out1, float* __restrict__ hT0, float* __restrict__ hT1)
{
    __shared__ __align__(16) float hbuf[2][DH];
    __shared__ __align__(16) float stage[8][DH];   // consumer: out0 ring
    __shared__ __align__(16) float ring[8][64];    // consumer: wx1b ring

    const int tid  = threadIdx.x;
    const int role = blockIdx.x >> 6;   // 0 = producer, 1 = consumer
    const int b    = blockIdx.x & 63;

    float*       out0b = g_out0 + (size_t)b * DS * DH;
    const float* wx0b  = g_wx0  + (size_t)b * DS * DH;
    float*       wx1ab = g_wx1a + (size_t)b * DS * 64;
    int*         p0    = g_prog + b * 32;
    int*         pwx1a = g_prog + b * 32 + 8;

    if (role == 0) {
        // ============================ PRODUCER ==============================
        if (tid < DH) {
            // ---- scan warps 0-3: one column per thread, zero waits ----
            const int j = tid;
            u64 uk[64];
            #pragma unroll
            for (int i = 0; i < 64; i++)
                uk[i] = pk2(u0[(size_t)(2*i) * DH + j], u0[(size_t)(2*i+1) * DH + j]);
            const float bgj  = bg0[j], buj = bu0[j];
            const float sz   = sigm_fast(zeta0[0]);
            const float sn   = sigm_fast(nu0[0]);
            const float gc   = fminf(fmaxf(gamma0[0], 0.f), 1.f);
            const float cadd = (1.f - gc) * lambd0[0];

            hbuf[0][j] = 0.f;
            float hold = 0.f;
            float wxA = wx0b[j], wxB = wx0b[DH + j];
            __syncthreads();

            #pragma unroll 1
            for (int s = 0; s < DS; s++) {
                float pre = mv128(hbuf[s & 1], uk) + wxA;
                float zg  = sigm_fast(pre + bgj);
                float th  = tanh_fast(pre + buj);
                float hn  = zg * hold + (sz * (1.f - zg) + sn) * th;
                float hc  = __fmaf_rn(gc, hn, cadd);
                hold = hc;
                hbuf[(s + 1) & 1][j] = hc;
                out0b[(size_t)s * DH + j] = hc;
                wxA = wxB;
                wxB = (s + 2 < DS) ? wx0b[(size_t)(s + 2) * DH + j] : 0.f;
                __syncthreads();
                if ((s & 7) == 7 && tid == 0) {
                    __threadfence();
                    st_rel(p0, s + 1);          // out0 rows <= s ready
                    st_rel(pwx1a, s);           // wx1a rows <= s-1 ready
                }
            }
            hT0[(size_t)b * DH + j] = hold;
            __syncthreads();                    // final bar (matches helpers)
            if (tid == 0) { __threadfence(); st_rel(pwx1a, DS); }
        } else {
            // ---- helper warps 4-7: wx1a[s-1] = h_s @ w1[:,0:64], local h ----
            const int ht = tid - 128;
            const int c  = ht >> 1;             // output col 0..63
            const int kh = ht & 1;              // k-half
            u64 uw[32];
            #pragma unroll
            for (int i = 0; i < 32; i++)
                uw[i] = pk2(w1[(size_t)(kh*64 + 2*i) * DH + c],
                            w1[(size_t)(kh*64 + 2*i + 1) * DH + c]);
            __syncthreads();

            #pragma unroll 1
            for (int s = 0; s < DS; s++) {
                u64 acc = mv64(&hbuf[s & 1][kh * 64], uw);
                float v = comb2(acc);
                if (kh == 0 && s > 0) wx1ab[(size_t)(s - 1) * 64 + c] = v;
                __syncthreads();
            }
            {   // epilogue: wx1a[DS-1] from h_DS (slot 0, DS even)
                u64 acc = mv64(&hbuf[0][kh * 64], uw);
                float v = comb2(acc);
                if (kh == 0) wx1ab[(size_t)(DS - 1) * 64 + c] = v;
            }
            __syncthreads();                    // final bar
        }
    } else {
        // ============================ CONSUMER ==============================
        if (tid < DH) {
            // ---- scan warps 0-3 ----
            const int j = tid;
            u64 uk[64];
            #pragma unroll
            for (int i = 0; i < 64; i++)
                uk[i] = pk2(u1[(size_t)(2*i) * DH + j], u1[(size_t)(2*i+1) * DH + j]);
            const float bgj  = bg1[j], buj = bu1[j];
            const float sz   = sigm_fast(zeta1[0]);
            const float sn   = sigm_fast(nu1[0]);
            const float gc   = fminf(fmaxf(gamma1[0], 0.f), 1.f);
            const float cadd = (1.f - gc) * lambd1[0];

            hbuf[0][j] = 0.f;
            if (tid == 0) { spin_ge(p0, 16); spin_ge(pwx1a, 10); }
            __syncthreads();                    // B1
            float wxA = 0.f, wxB = 0.f;
            if (j < 64) { wxA = wx1ab[j]; wxB = wx1ab[64 + j]; }
            __syncthreads();                    // B2
            __syncthreads();                    // B3

            float hold = 0.f;
            float* outb = out1 + (size_t)b * DS * DH;

            #pragma unroll 1
            for (int s = 0; s < DS; s++) {
                if ((s & 7) == 0 && s) {
                    if (tid == 0) {
                        int t1 = s + 16; if (t1 > DS) t1 = DS;
                        int t2 = s + 10; if (t2 > DS) t2 = DS;
                        spin_ge(p0, t1);
                        spin_ge(pwx1a, t2);
                    }
                    __syncthreads();
                }
                float wx = (j < 64) ? wxA : ring[s & 7][j - 64];
                float pre = mv128(hbuf[s & 1], uk) + wx;
                float zg  = sigm_fast(pre + bgj);
                float th  = tanh_fast(pre + buj);
                float hn  = zg * hold + (sz * (1.f - zg) + sn) * th;
                float hc  = __fmaf_rn(gc, hn, cadd);
                hold = hc;
                hbuf[(s + 1) & 1][j] = hc;
                outb[(size_t)s * DH + j] = hc;
                if (j < 64) {
                    wxA = wxB;
                    wxB = (s + 2 < DS) ? wx1ab[(size_t)(s + 2) * 64 + j] : 0.f;
                }
                __syncthreads();
            }
            hT1[(size_t)b * DH + j] = hold;
        } else {
            // ---- helper warps 4-7: wx1b[t] = out0[t] @ w1[:,64:128] --------
            const int ht  = tid - 128;          // 0..127
            const int c   = ht >> 1;            // 0..63 -> col 64+c
            const int kh  = ht & 1;
            const int col = 64 + c;
            u64 uw[32];
            #pragma unroll
            for (int i = 0; i < 32; i++)
                uw[i] = pk2(w1[(size_t)(kh*64 + 2*i) * DH + col],
                            w1[(size_t)(kh*64 + 2*i + 1) * DH + col]);
            __syncthreads();                    // B1 (spins done)

            // preload stage rows 0..3 + gPref = row 4
            {
                int row = ht >> 5, l = ht & 31;
                reinterpret_cast<float4*>(stage[row])[l] =
                    reinterpret_cast<const float4*>(out0b + (size_t)row * DH)[l];
            }
            float4 gPref = make_float4(0.f, 0.f, 0.f, 0.f);
            if (ht < 32)
                gPref = reinterpret_cast<const float4*>(out0b + (size_t)4 * DH)[ht];
            __syncthreads();                    // B2

            // precompute wx1b[0..2]
            #pragma unroll
            for (int r = 0; r < 3; r++) {
                u64 acc = mv64(&stage[r][kh * 64], uw);
                float v = comb2(acc);
                if (kh == 0) ring[r][c] = v;
            }
            __syncthreads();                    // B3

            #pragma unroll 1
            for (int s = 0; s < DS; s++) {
                if ((s & 7) == 0 && s) __syncthreads();     // match scan spin bar
                if (ht < 32) {
                    if (s + 4 < DS)
                        reinterpret_cast<float4*>(stage[(s + 4) & 7])[ht] = gPref;
                    gPref = (s + 5 < DS)
                          ? reinterpret_cast<const float4*>(out0b + (size_t)(s + 5) * DH)[ht]
                          : make_float4(0.f, 0.f, 0.f, 0.f);
                }
                if (s + 3 < DS) {
                    u64 acc = mv64(&stage[(s + 3) & 7][kh * 64], uw);
                    float v = comb2(acc);
                    if (kh == 0) ring[(s + 3) & 7][c] = v;
                }
                __syncthreads();
            }
        }
    }
}

// ============================================================================
extern "C" void kernel_launch(void* const* d_in, const int* in_sizes, int n_in,
                              void* d_out, int out_size)
{
    const float* x      = (const float*)d_in[0];
    const float* w0     = (const float*)d_in[1];
    const float* u0     = (const float*)d_in[2];
    const float* bg0    = (const float*)d_in[3];
    const float* bu0    = (const float*)d_in[4];
    const float* zeta0  = (const float*)d_in[5];
    const float* nu0    = (const float*)d_in[6];
    const float* lambd0 = (const float*)d_in[7];
    const float* gamma0 = (const float*)d_in[8];
    const float* w1     = (const float*)d_in[9];
    const float* u1     = (const float*)d_in[10];
    const float* bg1    = (const float*)d_in[11];
    const float* bu1    = (const float*)d_in[12];
    const float* zeta1  = (const float*)d_in[13];
    const float* nu1    = (const float*)d_in[14];
    const float* lambd1 = (const float*)d_in[15];
    const float* gamma1 = (const float*)d_in[16];
    (void)in_sizes; (void)n_in; (void)out_size;

    float* out = (float*)d_out;                    // out1: [B, S, H]
    float* hT0 = out + (size_t)DB * DS * DH;       // h_n[0]
    float* hT1 = hT0 + (size_t)DB * DH;            // h_n[1]

    void* p;
    cudaGetSymbolAddress(&p, g_wx0);
    float* wx0p = (float*)p;

    static int smem_set = 0;
    if (!smem_set) {
        cudaFuncSetAttribute(gemm_rows<DI>,
                             cudaFuncAttributeMaxDynamicSharedMemorySize, DI * DH * 4);
        smem_set = 1;
    }

    reset_kernel<<<2, 1024>>>();
    gemm_rows<DI><<<(DB * DS) / 256, 256, DI * DH * 4>>>(x, w0, wx0p);
    pipe_kernel<<<2 * DB, 256>>>(
        u0, u1, w1,
        bg0, bu0, zeta0, nu0, lambd0, gamma0,
        bg1, bu1, zeta1, nu1, lambd1, gamma1,
        out, hT0, hT1);
}